// round 6
// baseline (speedup 1.0000x reference)
#include <cuda_runtime.h>
#include <cuda_bf16.h>
#include <cstdint>

// v5: HMMA, 1 window per CTA, 256 threads, 8192 CTAs, 2 CTAs/SM.
// SW128 blocked-swizzle smem layout (16KB data tiles / 32KB weights, no pad).

#define OFF_XF 0        // f32 [128c][66t]  residual, final out
#define OFF_A  33792    // bf16 blk64: xn -> v[t][c]
#define OFF_B  50176    // bf16 blk64: q -> o -> y_hi
#define OFF_C  66560    // bf16 blk64: k -> y_lo
#define OFF_W  82944    // bf16 blk128: weight stage
#define SMEM_BYTES 115712

__device__ __align__(16) __nv_bfloat16 g_win[3 * 16384];
__device__ __align__(16) __nv_bfloat16 g_wout[16384];
__device__ __align__(16) __nv_bfloat16 g_wc_hi[16384];
__device__ __align__(16) __nv_bfloat16 g_wc_lo[16384];

// SW128 blocked byte offsets: r rows, cB byte-column. 128-row and 64-row tiles.
__host__ __device__ __forceinline__ uint32_t bl128(int r, int cB) {
    return ((r >> 3) << 10) + ((r & 7) << 7) + ((cB >> 7) << 14) +
           (((uint32_t)(cB & 127)) ^ (uint32_t)((r & 7) << 4));
}
__host__ __device__ __forceinline__ uint32_t bl64(int r, int cB) {
    return ((r >> 3) << 10) + ((r & 7) << 7) + ((cB >> 7) << 13) +
           (((uint32_t)(cB & 127)) ^ (uint32_t)((r & 7) << 4));
}

__global__ void convert_weights_kernel(const float* __restrict__ win,
                                       const float* __restrict__ wout,
                                       const float* __restrict__ wc) {
    int i = blockIdx.x * blockDim.x + threadIdx.x;
    if (i < 3 * 16384) {
        int o = i >> 7, c = i & 127;
        int blk = o >> 7, ol = o & 127;
        g_win[blk * 16384 + (bl128(ol, c * 2) >> 1)] = __float2bfloat16(win[i]);
    }
    if (i < 16384) {
        int o = i >> 7, c = i & 127;
        uint32_t d = bl128(o, c * 2) >> 1;
        g_wout[d] = __float2bfloat16(wout[i]);
        float f = wc[i];
        __nv_bfloat16 h = __float2bfloat16(f);
        g_wc_hi[d] = h;
        g_wc_lo[d] = __float2bfloat16(f - __bfloat162float(h));
    }
}

__device__ __forceinline__ void mma16816(float acc[4], uint32_t a0, uint32_t a1,
                                         uint32_t a2, uint32_t a3,
                                         uint32_t b0, uint32_t b1) {
    asm volatile(
        "mma.sync.aligned.m16n8k16.row.col.f32.bf16.bf16.f32 "
        "{%0,%1,%2,%3},{%4,%5,%6,%7},{%8,%9},{%0,%1,%2,%3};\n"
        : "+f"(acc[0]), "+f"(acc[1]), "+f"(acc[2]), "+f"(acc[3])
        : "r"(a0), "r"(a1), "r"(a2), "r"(a3), "r"(b0), "r"(b1));
}
__device__ __forceinline__ uint32_t packbf(float lo, float hi) {
    uint32_t r;
    asm("cvt.rn.bf16x2.f32 %0, %1, %2;" : "=r"(r) : "f"(hi), "f"(lo));
    return r;
}
__device__ __forceinline__ void ldsm4(uint32_t& r0, uint32_t& r1, uint32_t& r2,
                                      uint32_t& r3, uint32_t addr) {
    asm volatile("ldmatrix.sync.aligned.m8n8.x4.shared.b16 {%0,%1,%2,%3},[%4];"
                 : "=r"(r0), "=r"(r1), "=r"(r2), "=r"(r3) : "r"(addr));
}
__device__ __forceinline__ void ldsm4t(uint32_t& r0, uint32_t& r1, uint32_t& r2,
                                       uint32_t& r3, uint32_t addr) {
    asm volatile("ldmatrix.sync.aligned.m8n8.x4.trans.shared.b16 {%0,%1,%2,%3},[%4];"
                 : "=r"(r0), "=r"(r1), "=r"(r2), "=r"(r3) : "r"(addr));
}
__device__ __forceinline__ uint32_t su32(const void* p) {
    return (uint32_t)__cvta_generic_to_shared(p);
}

#define CPA16(dst, src) \
    asm volatile("cp.async.cg.shared.global [%0],[%1],16;" ::"r"(dst), "l"(src))
#define CPA8(dst, src) \
    asm volatile("cp.async.ca.shared.global [%0],[%1],8;" ::"r"(dst), "l"(src))
#define CPC()  asm volatile("cp.async.commit_group;")
#define CPW0() asm volatile("cp.async.wait_group 0;")

// stage 32KB pre-swizzled weight (linear), 8 x 16B per thread
__device__ __forceinline__ void stage_w(const __nv_bfloat16* __restrict__ src,
                                        uint32_t dstu, int tid) {
#pragma unroll
    for (int it = 0; it < 8; it++) {
        int idx = it * 256 + tid;
        CPA16(dstu + idx * 16, src + idx * 8);
    }
    CPC();
}

// D[32][32] += A64[rows mq*32..][128] @ W128[rows nq*32..][128]^T
__device__ __forceinline__ void gemm64(uint32_t Au, uint32_t Wu,
                                       float acc[2][4][4], int mq, int nq,
                                       int l16, int lh) {
#pragma unroll
    for (int k = 0; k < 8; k++) {
        int cB = k * 32 + lh * 16;
        uint32_t a0, a1, a2, a3, e0, e1, e2, e3;
        uint32_t b0, b1, b2, b3, c0, c1, c2, c3;
        ldsm4(a0, a1, a2, a3, Au + bl64(mq * 32 + l16, cB));
        ldsm4(e0, e1, e2, e3, Au + bl64(mq * 32 + 16 + l16, cB));
        ldsm4(b0, b1, b2, b3, Wu + bl128(nq * 32 + l16, cB));
        ldsm4(c0, c1, c2, c3, Wu + bl128(nq * 32 + 16 + l16, cB));
        mma16816(acc[0][0], a0, a1, a2, a3, b0, b2);
        mma16816(acc[0][1], a0, a1, a2, a3, b1, b3);
        mma16816(acc[0][2], a0, a1, a2, a3, c0, c2);
        mma16816(acc[0][3], a0, a1, a2, a3, c1, c3);
        mma16816(acc[1][0], e0, e1, e2, e3, b0, b2);
        mma16816(acc[1][1], e0, e1, e2, e3, b1, b3);
        mma16816(acc[1][2], e0, e1, e2, e3, c0, c2);
        mma16816(acc[1][3], e0, e1, e2, e3, c1, c3);
    }
}

__global__ void __launch_bounds__(256, 2)
fused_wsa3d_kernel(const float* __restrict__ x,
                   const float* __restrict__ ln_g, const float* __restrict__ ln_b,
                   const float* __restrict__ in_b, const float* __restrict__ out_b,
                   const float* __restrict__ conv_b,
                   float* __restrict__ out) {
    extern __shared__ char sm[];
    float* xf = (float*)(sm + OFF_XF);  // [128][66]

    const int tid = threadIdx.x;
    const int warp = tid >> 5, lane = tid & 31;
    const int g = lane >> 2, q2 = (lane & 3) * 2;
    const int l16 = lane & 15, lh = lane >> 4;
    const int mq = warp & 1, nq = warp >> 1;  // 2x4 warp grid

    const uint32_t s_xf = su32(sm + OFF_XF);
    const uint32_t s_A = su32(sm + OFF_A);
    const uint32_t s_B = su32(sm + OFF_B);
    const uint32_t s_C = su32(sm + OFF_C);
    const uint32_t s_W = su32(sm + OFF_W);

    const int widx = blockIdx.x;
    const int b = widx >> 12;
    const int r3 = widx & 4095;
    const int d0 = (r3 >> 8) * 4;
    const int h0 = ((r3 >> 4) & 15) * 4;
    const int w0 = (r3 & 15) * 4;
    const float* xb = x + (size_t)b * 128 * 262144;

    // ---- x window load (8B cp.async) + Wq stage ----
#pragma unroll
    for (int it = 0; it < 16; it++) {
        int idx = it * 256 + tid;
        int c = idx >> 5, p = idx & 31;
        int row = p >> 1, wpair = p & 1;
        int dd = row >> 2, hh = row & 3;
        CPA8(s_xf + (c * 66 + row * 4 + wpair * 2) * 4,
             xb + (size_t)c * 262144 + (size_t)(d0 + dd) * 4096 +
                 (h0 + hh) * 64 + w0 + wpair * 2);
    }
    stage_w(g_win, s_W, tid);
    CPW0();
    __syncthreads();

    // ---- LayerNorm: 4 threads/token, write xn -> A (blk64) ----
    {
        int t = tid >> 2, j = tid & 3;
        float vv[32];
        float s = 0.f, s2 = 0.f;
#pragma unroll
        for (int i = 0; i < 32; i++) {
            vv[i] = xf[(j * 32 + i) * 66 + t];
            s += vv[i]; s2 += vv[i] * vv[i];
        }
        s  += __shfl_xor_sync(0xffffffffu, s, 1);
        s  += __shfl_xor_sync(0xffffffffu, s, 2);
        s2 += __shfl_xor_sync(0xffffffffu, s2, 1);
        s2 += __shfl_xor_sync(0xffffffffu, s2, 2);
        float mu = s * (1.f / 128.f);
        float rstd = rsqrtf(s2 * (1.f / 128.f) - mu * mu + 1e-5f);
#pragma unroll
        for (int m = 0; m < 16; m++) {
            int c = j * 32 + 2 * m;
            float v0 = (vv[2 * m] - mu) * rstd * __ldg(ln_g + c) + __ldg(ln_b + c);
            float v1 = (vv[2 * m + 1] - mu) * rstd * __ldg(ln_g + c + 1) + __ldg(ln_b + c + 1);
            *(uint32_t*)(sm + OFF_A + bl64(t, c * 2)) = packbf(v0, v1);
        }
    }
    __syncthreads();

    // ================= QKV: three GEMMs xn(A) @ W =================
#pragma unroll 1
    for (int qkv = 0; qkv < 3; qkv++) {
        float acc[2][4][4] = {};
        gemm64(s_A, s_W, acc, mq, nq, l16, lh);
        __syncthreads();  // all W reads & (for V) all A reads done
        if (qkv < 2) stage_w(g_win + (qkv + 1) * 16384, s_W, tid);
        else         stage_w(g_wout, s_W, tid);
        const float* bp = in_b + qkv * 128;
        uint32_t dst = (qkv == 0) ? s_B : (qkv == 1) ? s_C : s_A;
#pragma unroll
        for (int nt = 0; nt < 4; nt++) {
            int cc = nq * 32 + nt * 8 + q2;
            float b0v = __ldg(bp + cc), b1v = __ldg(bp + cc + 1);
#pragma unroll
            for (int m = 0; m < 2; m++) {
                int ra = mq * 32 + m * 16 + g, rb = ra + 8;
                *(uint32_t*)(sm + (dst - s_xf) + bl64(ra, cc * 2)) =
                    packbf(acc[m][nt][0] + b0v, acc[m][nt][1] + b1v);
                *(uint32_t*)(sm + (dst - s_xf) + bl64(rb, cc * 2)) =
                    packbf(acc[m][nt][2] + b0v, acc[m][nt][3] + b1v);
            }
        }
        CPW0();
        __syncthreads();
    }

    // ================= Attention: 16 tasks, 2/warp; o -> B (over q) =========
#pragma unroll 1
    for (int ti = 0; ti < 2; ti++) {
        const int task = warp + ti * 8;
        const int head = task >> 2, mt = task & 3;
        const int cqk = head * 64;  // byte col base of this head

        float P[8][4] = {};
#pragma unroll
        for (int k2 = 0; k2 < 2; k2++) {
            uint32_t a0, a1, a2, a3;
            ldsm4(a0, a1, a2, a3, s_B + bl64(mt * 16 + l16, cqk + k2 * 32 + lh * 16));
#pragma unroll
            for (int p = 0; p < 4; p++) {
                uint32_t b0, b1, b2, b3;
                ldsm4(b0, b1, b2, b3,
                      s_C + bl64(p * 16 + l16, cqk + k2 * 32 + lh * 16));
                mma16816(P[2 * p], a0, a1, a2, a3, b0, b2);
                mma16816(P[2 * p + 1], a0, a1, a2, a3, b1, b3);
            }
        }
        const float scale = 0.17677669529663687f;  // 1/sqrt(32)
        float mA = -1e30f, mB = -1e30f;
#pragma unroll
        for (int nt = 0; nt < 8; nt++) {
            mA = fmaxf(mA, fmaxf(P[nt][0], P[nt][1]));
            mB = fmaxf(mB, fmaxf(P[nt][2], P[nt][3]));
        }
        mA = fmaxf(mA, __shfl_xor_sync(0xffffffffu, mA, 1));
        mA = fmaxf(mA, __shfl_xor_sync(0xffffffffu, mA, 2));
        mB = fmaxf(mB, __shfl_xor_sync(0xffffffffu, mB, 1));
        mB = fmaxf(mB, __shfl_xor_sync(0xffffffffu, mB, 2));
        float sA = 0.f, sB = 0.f;
#pragma unroll
        for (int nt = 0; nt < 8; nt++) {
            float e0 = __expf((P[nt][0] - mA) * scale);
            float e1 = __expf((P[nt][1] - mA) * scale);
            float e2 = __expf((P[nt][2] - mB) * scale);
            float e3 = __expf((P[nt][3] - mB) * scale);
            P[nt][0] = e0; P[nt][1] = e1; P[nt][2] = e2; P[nt][3] = e3;
            sA += e0 + e1; sB += e2 + e3;
        }
        sA += __shfl_xor_sync(0xffffffffu, sA, 1);
        sA += __shfl_xor_sync(0xffffffffu, sA, 2);
        sB += __shfl_xor_sync(0xffffffffu, sB, 1);
        sB += __shfl_xor_sync(0xffffffffu, sB, 2);
        float iA = 1.f / sA, iB = 1.f / sB;

        float accO[4][4] = {};
#pragma unroll
        for (int ks = 0; ks < 4; ks++) {
            uint32_t a0 = packbf(P[2 * ks][0] * iA, P[2 * ks][1] * iA);
            uint32_t a1 = packbf(P[2 * ks][2] * iB, P[2 * ks][3] * iB);
            uint32_t a2 = packbf(P[2 * ks + 1][0] * iA, P[2 * ks + 1][1] * iA);
            uint32_t a3 = packbf(P[2 * ks + 1][2] * iB, P[2 * ks + 1][3] * iB);
            uint32_t r0, r1, r2, r3;
            // V[t][c] via trans-ldsm -> B-frags for P@V
            ldsm4t(r0, r1, r2, r3, s_A + bl64(ks * 16 + l16, cqk + lh * 16));
            mma16816(accO[0], a0, a1, a2, a3, r0, r1);
            mma16816(accO[1], a0, a1, a2, a3, r2, r3);
            ldsm4t(r0, r1, r2, r3, s_A + bl64(ks * 16 + l16, cqk + 32 + lh * 16));
            mma16816(accO[2], a0, a1, a2, a3, r0, r1);
            mma16816(accO[3], a0, a1, a2, a3, r2, r3);
        }
        int ta = mt * 16 + g, tb = ta + 8;
#pragma unroll
        for (int nt = 0; nt < 4; nt++) {
            int cc = head * 32 + nt * 8 + q2;
            *(uint32_t*)(sm + OFF_B + bl64(ta, cc * 2)) = packbf(accO[nt][0], accO[nt][1]);
            *(uint32_t*)(sm + OFF_B + bl64(tb, cc * 2)) = packbf(accO[nt][2], accO[nt][3]);
        }
    }
    __syncthreads();

    // ================= out_proj: o(B) @ Wo(W) ; y_hi->B, y_lo->C ===========
    {
        float acc[2][4][4] = {};
        gemm64(s_B, s_W, acc, mq, nq, l16, lh);
        __syncthreads();  // W + B reads done
        stage_w(g_wc_hi, s_W, tid);
#pragma unroll
        for (int nt = 0; nt < 4; nt++) {
            int cc = nq * 32 + nt * 8 + q2;
            float b0v = __ldg(out_b + cc), b1v = __ldg(out_b + cc + 1);
#pragma unroll
            for (int m = 0; m < 2; m++) {
                int ra = mq * 32 + m * 16 + g, rb = ra + 8;
                float y00 = acc[m][nt][0] + b0v + xf[cc * 66 + ra];
                float y01 = acc[m][nt][1] + b1v + xf[(cc + 1) * 66 + ra];
                float y10 = acc[m][nt][2] + b0v + xf[cc * 66 + rb];
                float y11 = acc[m][nt][3] + b1v + xf[(cc + 1) * 66 + rb];
                float h00 = __bfloat162float(__float2bfloat16(y00));
                float h01 = __bfloat162float(__float2bfloat16(y01));
                float h10 = __bfloat162float(__float2bfloat16(y10));
                float h11 = __bfloat162float(__float2bfloat16(y11));
                *(uint32_t*)(sm + OFF_B + bl64(ra, cc * 2)) = packbf(y00, y01);
                *(uint32_t*)(sm + OFF_B + bl64(rb, cc * 2)) = packbf(y10, y11);
                *(uint32_t*)(sm + OFF_C + bl64(ra, cc * 2)) = packbf(y00 - h00, y01 - h01);
                *(uint32_t*)(sm + OFF_C + bl64(rb, cc * 2)) = packbf(y10 - h10, y11 - h11);
            }
        }
        CPW0();
        __syncthreads();
    }

    // ================= conv: y_hi@Whi + y_lo@Whi + y_hi@Wlo ================
    {
        float acc[2][4][4] = {};
        gemm64(s_B, s_W, acc, mq, nq, l16, lh);
        gemm64(s_C, s_W, acc, mq, nq, l16, lh);
        __syncthreads();  // Whi reads done
        stage_w(g_wc_lo, s_W, tid);
        CPW0();
        __syncthreads();
        gemm64(s_B, s_W, acc, mq, nq, l16, lh);

        // epilogue: out = acc + conv_b + x, in place into xf
#pragma unroll
        for (int nt = 0; nt < 4; nt++) {
            int cc = nq * 32 + nt * 8 + q2;
            float b0v = __ldg(conv_b + cc), b1v = __ldg(conv_b + cc + 1);
#pragma unroll
            for (int m = 0; m < 2; m++) {
                int ra = mq * 32 + m * 16 + g, rb = ra + 8;
                xf[cc * 66 + ra]       = acc[m][nt][0] + b0v + xf[cc * 66 + ra];
                xf[(cc + 1) * 66 + ra] = acc[m][nt][1] + b1v + xf[(cc + 1) * 66 + ra];
                xf[cc * 66 + rb]       = acc[m][nt][2] + b0v + xf[cc * 66 + rb];
                xf[(cc + 1) * 66 + rb] = acc[m][nt][3] + b1v + xf[(cc + 1) * 66 + rb];
            }
        }
    }
    __syncthreads();

    // ---- store (float2) ----
    float* ob = out + (size_t)b * 128 * 262144;
#pragma unroll
    for (int it = 0; it < 16; it++) {
        int idx = it * 256 + tid;
        int c = idx >> 5, p = idx & 31;
        int row = p >> 1, wpair = p & 1;
        int dd = row >> 2, hh = row & 3;
        *(float2*)(ob + (size_t)c * 262144 + (size_t)(d0 + dd) * 4096 +
                   (h0 + hh) * 64 + w0 + wpair * 2) =
            *(float2*)(xf + c * 66 + row * 4 + wpair * 2);
    }
}

extern "C" void kernel_launch(void* const* d_in, const int* in_sizes, int n_in,
                              void* d_out, int out_size) {
    const float* x      = (const float*)d_in[0];
    const float* ln_g   = (const float*)d_in[1];
    const float* ln_b   = (const float*)d_in[2];
    const float* in_w   = (const float*)d_in[3];
    const float* in_b   = (const float*)d_in[4];
    const float* out_w  = (const float*)d_in[5];
    const float* out_b  = (const float*)d_in[6];
    const float* conv_w = (const float*)d_in[7];
    const float* conv_b = (const float*)d_in[8];
    float* out = (float*)d_out;

    convert_weights_kernel<<<192, 256>>>(in_w, out_w, conv_w);

    cudaFuncSetAttribute(fused_wsa3d_kernel,
                         cudaFuncAttributeMaxDynamicSharedMemorySize, SMEM_BYTES);
    cudaFuncSetAttribute(fused_wsa3d_kernel,
                         cudaFuncAttributePreferredSharedMemoryCarveout, 100);
    fused_wsa3d_kernel<<<8192, 256, SMEM_BYTES>>>(x, ln_g, ln_b, in_b, out_b,
                                                  conv_b, out);
}

// round 7
// speedup vs baseline: 1.5156x; 1.5156x over previous
#include <cuda_runtime.h>
#include <cuda_bf16.h>
#include <cstdint>

// v6: HMMA, 2 windows/CTA, 512 thr, 4096 CTAs. SW128 blocked tiles (no pad),
// double-buffered weights (zero exposed stages), strength-reduced swizzle.

#define OFF_XF 0        // f32 [128c][132t] residual
#define OFF_W0 67584    // bf16 blk 32KB weight buf 0
#define OFF_W1 100352   // bf16 blk 32KB weight buf 1
#define OFF_AB 133120   // xn -> v -> (free)
#define OFF_QS 165888   // q -> o -> y_hi
#define OFF_KS 198656   // k -> y_lo
#define SMEM_BYTES 231424

__device__ __align__(16) __nv_bfloat16 g_win[3 * 16384];
__device__ __align__(16) __nv_bfloat16 g_wout[16384];
__device__ __align__(16) __nv_bfloat16 g_wc_hi[16384];
__device__ __align__(16) __nv_bfloat16 g_wc_lo[16384];

// SW128 blocked byte offset: 128-row x 256B tile, 8-row 1KB atoms, 16KB atom-col
__host__ __device__ __forceinline__ uint32_t bl128(int r, int cB) {
    return ((r >> 3) << 10) + ((r & 7) << 7) + ((cB >> 7) << 14) +
           (((uint32_t)(cB & 127)) ^ (uint32_t)((r & 7) << 4));
}

__global__ void convert_weights_kernel(const float* __restrict__ win,
                                       const float* __restrict__ wout,
                                       const float* __restrict__ wc) {
    int i = blockIdx.x * blockDim.x + threadIdx.x;
    if (i < 3 * 16384) {
        int o = i >> 7, c = i & 127;
        int blk = o >> 7, ol = o & 127;
        g_win[blk * 16384 + (bl128(ol, c * 2) >> 1)] = __float2bfloat16(win[i]);
    }
    if (i < 16384) {
        int o = i >> 7, c = i & 127;
        uint32_t d = bl128(o, c * 2) >> 1;
        g_wout[d] = __float2bfloat16(wout[i]);
        float f = wc[i];
        __nv_bfloat16 h = __float2bfloat16(f);
        g_wc_hi[d] = h;
        g_wc_lo[d] = __float2bfloat16(f - __bfloat162float(h));
    }
}

__device__ __forceinline__ void mma16816(float acc[4], uint32_t a0, uint32_t a1,
                                         uint32_t a2, uint32_t a3,
                                         uint32_t b0, uint32_t b1) {
    asm volatile(
        "mma.sync.aligned.m16n8k16.row.col.f32.bf16.bf16.f32 "
        "{%0,%1,%2,%3},{%4,%5,%6,%7},{%8,%9},{%0,%1,%2,%3};\n"
        : "+f"(acc[0]), "+f"(acc[1]), "+f"(acc[2]), "+f"(acc[3])
        : "r"(a0), "r"(a1), "r"(a2), "r"(a3), "r"(b0), "r"(b1));
}
__device__ __forceinline__ uint32_t packbf(float lo, float hi) {
    uint32_t r;
    asm("cvt.rn.bf16x2.f32 %0, %1, %2;" : "=r"(r) : "f"(hi), "f"(lo));
    return r;
}
__device__ __forceinline__ void ldsm4(uint32_t& r0, uint32_t& r1, uint32_t& r2,
                                      uint32_t& r3, uint32_t addr) {
    asm volatile("ldmatrix.sync.aligned.m8n8.x4.shared.b16 {%0,%1,%2,%3},[%4];"
                 : "=r"(r0), "=r"(r1), "=r"(r2), "=r"(r3) : "r"(addr));
}
__device__ __forceinline__ void ldsm4t(uint32_t& r0, uint32_t& r1, uint32_t& r2,
                                       uint32_t& r3, uint32_t addr) {
    asm volatile("ldmatrix.sync.aligned.m8n8.x4.trans.shared.b16 {%0,%1,%2,%3},[%4];"
                 : "=r"(r0), "=r"(r1), "=r"(r2), "=r"(r3) : "r"(addr));
}
__device__ __forceinline__ uint32_t su32(const void* p) {
    return (uint32_t)__cvta_generic_to_shared(p);
}

#define CPA16(dst, src) \
    asm volatile("cp.async.cg.shared.global [%0],[%1],16;" ::"r"(dst), "l"(src))
#define CPC()  asm volatile("cp.async.commit_group;")
#define CPW0() asm volatile("cp.async.wait_group 0;")

// linear 32KB copy of pre-swizzled weights
__device__ __forceinline__ void stage_w(const __nv_bfloat16* __restrict__ src,
                                        uint32_t dstu, int tid) {
#pragma unroll
    for (int it = 0; it < 4; it++) {
        int idx = it * 512 + tid;
        CPA16(dstu + idx * 16, src + idx * 8);
    }
    CPC();
}

// D[32][32] += A[128x128 blk]@W^T; precomputed frag offsets, XOR k-stepping
__device__ __forceinline__ void gemm128(uint32_t Au, uint32_t Wu,
                                        uint32_t oA0, uint32_t oA1,
                                        uint32_t oW0, uint32_t oW1,
                                        float acc[2][4][4]) {
#pragma unroll
    for (int k = 0; k < 8; k++) {
        const uint32_t xk = (uint32_t)((k & 3) << 5);
        const uint32_t st = (uint32_t)((k >> 2) << 14);
        uint32_t a0, a1, a2, a3, e0, e1, e2, e3;
        uint32_t b0, b1, b2, b3, c0, c1, c2, c3;
        ldsm4(a0, a1, a2, a3, Au + ((oA0 ^ xk) + st));
        ldsm4(e0, e1, e2, e3, Au + ((oA1 ^ xk) + st));
        ldsm4(b0, b1, b2, b3, Wu + ((oW0 ^ xk) + st));
        ldsm4(c0, c1, c2, c3, Wu + ((oW1 ^ xk) + st));
        mma16816(acc[0][0], a0, a1, a2, a3, b0, b2);
        mma16816(acc[0][1], a0, a1, a2, a3, b1, b3);
        mma16816(acc[0][2], a0, a1, a2, a3, c0, c2);
        mma16816(acc[0][3], a0, a1, a2, a3, c1, c3);
        mma16816(acc[1][0], e0, e1, e2, e3, b0, b2);
        mma16816(acc[1][1], e0, e1, e2, e3, b1, b3);
        mma16816(acc[1][2], e0, e1, e2, e3, c0, c2);
        mma16816(acc[1][3], e0, e1, e2, e3, c1, c3);
    }
}

__global__ void __launch_bounds__(512, 1)
fused_wsa3d_kernel(const float* __restrict__ x,
                   const float* __restrict__ ln_g, const float* __restrict__ ln_b,
                   const float* __restrict__ in_b, const float* __restrict__ out_b,
                   const float* __restrict__ conv_b,
                   float* __restrict__ out) {
    extern __shared__ char sm[];
    float* xf = (float*)(sm + OFF_XF);  // [128][132]

    const int tid = threadIdx.x;
    const int warp = tid >> 5, lane = tid & 31;
    const int g = lane >> 2, q2 = (lane & 3) * 2;
    const int l16 = lane & 15, lh = lane >> 4;
    const int mq = warp & 3, nq = warp >> 2;  // 4x4 warp grid

    const uint32_t s_xf = su32(sm);
    const uint32_t s_w0 = s_xf + OFF_W0, s_w1 = s_xf + OFF_W1;
    const uint32_t s_ab = s_xf + OFF_AB, s_qs = s_xf + OFF_QS;
    const uint32_t s_ks = s_xf + OFF_KS;

    // precomputed fragment offsets (per-thread constants)
    const uint32_t oA0 = bl128(mq * 32 + l16, lh * 16);
    const uint32_t oA1 = bl128(mq * 32 + 16 + l16, lh * 16);
    const uint32_t oW0 = bl128(nq * 32 + l16, lh * 16);
    const uint32_t oW1 = bl128(nq * 32 + 16 + l16, lh * 16);

    const int widx = blockIdx.x;
    const int b = widx >> 11;
    const int r = widx & 2047;
    const int d0 = (r >> 7) * 4, h0 = ((r >> 3) & 15) * 4, wp = (r & 7) * 8;
    const float* xb = x + (size_t)b * 128 * 262144;

    // ---- x load (2 windows) + Wq ----
#pragma unroll
    for (int it = 0; it < 8; it++) {
        int idx = it * 512 + tid;
        int c = idx >> 5, rem = idx & 31;
        int win = rem >> 4, row = rem & 15;
        int dd = row >> 2, hh = row & 3;
        CPA16(s_xf + (c * 132 + win * 64 + row * 4) * 4,
              xb + (size_t)c * 262144 + (size_t)(d0 + dd) * 4096 +
                  (h0 + hh) * 64 + wp + win * 4);
    }
    CPC();
    stage_w(g_win, s_w0, tid);
    CPW0();
    __syncthreads();

    // ---- LayerNorm -> xn (AB) ----
    {
        int t = tid >> 2, j = tid & 3;
        float vv[32];
        float s = 0.f, s2 = 0.f;
#pragma unroll
        for (int i = 0; i < 32; i++) {
            vv[i] = xf[(j * 32 + i) * 132 + t];
            s += vv[i]; s2 += vv[i] * vv[i];
        }
        s  += __shfl_xor_sync(0xffffffffu, s, 1);
        s  += __shfl_xor_sync(0xffffffffu, s, 2);
        s2 += __shfl_xor_sync(0xffffffffu, s2, 1);
        s2 += __shfl_xor_sync(0xffffffffu, s2, 2);
        float mu = s * (1.f / 128.f);
        float rstd = rsqrtf(s2 * (1.f / 128.f) - mu * mu + 1e-5f);
#pragma unroll
        for (int m = 0; m < 16; m++) {
            int c = j * 32 + 2 * m;
            float v0 = (vv[2 * m] - mu) * rstd * __ldg(ln_g + c) + __ldg(ln_b + c);
            float v1 = (vv[2 * m + 1] - mu) * rstd * __ldg(ln_g + c + 1) + __ldg(ln_b + c + 1);
            *(uint32_t*)(sm + OFF_AB + bl128(t, c * 2)) = packbf(v0, v1);
        }
    }
    __syncthreads();

    // ================= Q: stage Wk; gemm(AB,W0) -> QS =================
    stage_w(g_win + 16384, s_w1, tid);
    {
        float acc[2][4][4] = {};
        gemm128(s_ab, s_w0, oA0, oA1, oW0, oW1, acc);
#pragma unroll
        for (int nt = 0; nt < 4; nt++) {
            int cc = nq * 32 + nt * 8 + q2;
            float b0v = __ldg(in_b + cc), b1v = __ldg(in_b + cc + 1);
#pragma unroll
            for (int m = 0; m < 2; m++) {
                int ra = mq * 32 + m * 16 + g, rb = ra + 8;
                *(uint32_t*)(sm + OFF_QS + bl128(ra, cc * 2)) =
                    packbf(acc[m][nt][0] + b0v, acc[m][nt][1] + b1v);
                *(uint32_t*)(sm + OFF_QS + bl128(rb, cc * 2)) =
                    packbf(acc[m][nt][2] + b0v, acc[m][nt][3] + b1v);
            }
        }
    }
    CPW0();
    __syncthreads();

    // ================= K: stage Wv; gemm(AB,W1) -> KS =================
    stage_w(g_win + 32768, s_w0, tid);
    {
        float acc[2][4][4] = {};
        gemm128(s_ab, s_w1, oA0, oA1, oW0, oW1, acc);
#pragma unroll
        for (int nt = 0; nt < 4; nt++) {
            int cc = nq * 32 + nt * 8 + q2;
            float b0v = __ldg(in_b + 128 + cc), b1v = __ldg(in_b + 128 + cc + 1);
#pragma unroll
            for (int m = 0; m < 2; m++) {
                int ra = mq * 32 + m * 16 + g, rb = ra + 8;
                *(uint32_t*)(sm + OFF_KS + bl128(ra, cc * 2)) =
                    packbf(acc[m][nt][0] + b0v, acc[m][nt][1] + b1v);
                *(uint32_t*)(sm + OFF_KS + bl128(rb, cc * 2)) =
                    packbf(acc[m][nt][2] + b0v, acc[m][nt][3] + b1v);
            }
        }
    }
    CPW0();
    __syncthreads();

    // ================= V: stage Wo; gemm(AB,W0); v -> AB ==============
    stage_w(g_wout, s_w1, tid);
    {
        float acc[2][4][4] = {};
        gemm128(s_ab, s_w0, oA0, oA1, oW0, oW1, acc);
        __syncthreads();  // all xn reads done before v overwrite
#pragma unroll
        for (int nt = 0; nt < 4; nt++) {
            int cc = nq * 32 + nt * 8 + q2;
            float b0v = __ldg(in_b + 256 + cc), b1v = __ldg(in_b + 256 + cc + 1);
#pragma unroll
            for (int m = 0; m < 2; m++) {
                int ra = mq * 32 + m * 16 + g, rb = ra + 8;
                *(uint32_t*)(sm + OFF_AB + bl128(ra, cc * 2)) =
                    packbf(acc[m][nt][0] + b0v, acc[m][nt][1] + b1v);
                *(uint32_t*)(sm + OFF_AB + bl128(rb, cc * 2)) =
                    packbf(acc[m][nt][2] + b0v, acc[m][nt][3] + b1v);
            }
        }
    }
    CPW0();
    __syncthreads();

    // ============ Attention: stage Whi; 32 tasks, o -> QS in place =========
    stage_w(g_wc_hi, s_w0, tid);
#pragma unroll 1
    for (int ti = 0; ti < 2; ti++) {
        const int task = warp + ti * 16;
        const int win = task >> 4, head = (task >> 2) & 3, mt = task & 3;
        const uint32_t oQ = bl128(win * 64 + mt * 16 + l16, head * 64 + lh * 16);
        const uint32_t oK = bl128(win * 64 + l16, head * 64 + lh * 16);
        const uint32_t oV = oK;  // same row/col pattern, different buffer

        float P[8][4] = {};
#pragma unroll
        for (int k2 = 0; k2 < 2; k2++) {
            uint32_t a0, a1, a2, a3;
            ldsm4(a0, a1, a2, a3, s_qs + (oQ ^ (k2 << 5)));
#pragma unroll
            for (int p = 0; p < 4; p++) {
                uint32_t b0, b1, b2, b3;
                ldsm4(b0, b1, b2, b3, s_ks + ((oK + p * 2048) ^ (k2 << 5)));
                mma16816(P[2 * p], a0, a1, a2, a3, b0, b2);
                mma16816(P[2 * p + 1], a0, a1, a2, a3, b1, b3);
            }
        }
        const float scale = 0.17677669529663687f;  // 1/sqrt(32)
        float mA = -1e30f, mB = -1e30f;
#pragma unroll
        for (int nt = 0; nt < 8; nt++) {
            mA = fmaxf(mA, fmaxf(P[nt][0], P[nt][1]));
            mB = fmaxf(mB, fmaxf(P[nt][2], P[nt][3]));
        }
        mA = fmaxf(mA, __shfl_xor_sync(0xffffffffu, mA, 1));
        mA = fmaxf(mA, __shfl_xor_sync(0xffffffffu, mA, 2));
        mB = fmaxf(mB, __shfl_xor_sync(0xffffffffu, mB, 1));
        mB = fmaxf(mB, __shfl_xor_sync(0xffffffffu, mB, 2));
        float sA = 0.f, sB = 0.f;
#pragma unroll
        for (int nt = 0; nt < 8; nt++) {
            float e0 = __expf((P[nt][0] - mA) * scale);
            float e1 = __expf((P[nt][1] - mA) * scale);
            float e2 = __expf((P[nt][2] - mB) * scale);
            float e3 = __expf((P[nt][3] - mB) * scale);
            P[nt][0] = e0; P[nt][1] = e1; P[nt][2] = e2; P[nt][3] = e3;
            sA += e0 + e1; sB += e2 + e3;
        }
        sA += __shfl_xor_sync(0xffffffffu, sA, 1);
        sA += __shfl_xor_sync(0xffffffffu, sA, 2);
        sB += __shfl_xor_sync(0xffffffffu, sB, 1);
        sB += __shfl_xor_sync(0xffffffffu, sB, 2);
        float iA = 1.f / sA, iB = 1.f / sB;

        float accO[4][4] = {};
#pragma unroll
        for (int ks = 0; ks < 4; ks++) {
            uint32_t a0 = packbf(P[2 * ks][0] * iA, P[2 * ks][1] * iA);
            uint32_t a1 = packbf(P[2 * ks][2] * iB, P[2 * ks][3] * iB);
            uint32_t a2 = packbf(P[2 * ks + 1][0] * iA, P[2 * ks + 1][1] * iA);
            uint32_t a3 = packbf(P[2 * ks + 1][2] * iB, P[2 * ks + 1][3] * iB);
            uint32_t r0, r1, r2, r3;
            ldsm4t(r0, r1, r2, r3, s_ab + (oV + ks * 2048));
            mma16816(accO[0], a0, a1, a2, a3, r0, r1);
            mma16816(accO[1], a0, a1, a2, a3, r2, r3);
            ldsm4t(r0, r1, r2, r3, s_ab + ((oV + ks * 2048) ^ 32));
            mma16816(accO[2], a0, a1, a2, a3, r0, r1);
            mma16816(accO[3], a0, a1, a2, a3, r2, r3);
        }
        int ta = win * 64 + mt * 16 + g, tb = ta + 8;
#pragma unroll
        for (int nt = 0; nt < 4; nt++) {
            int cc = head * 32 + nt * 8 + q2;
            *(uint32_t*)(sm + OFF_QS + bl128(ta, cc * 2)) = packbf(accO[nt][0], accO[nt][1]);
            *(uint32_t*)(sm + OFF_QS + bl128(tb, cc * 2)) = packbf(accO[nt][2], accO[nt][3]);
        }
    }
    CPW0();
    __syncthreads();

    // ============ out_proj: gemm(QS=o, W1=Wo); y_hi->QS, y_lo->KS ==========
    {
        float acc[2][4][4] = {};
        gemm128(s_qs, s_w1, oA0, oA1, oW0, oW1, acc);
        __syncthreads();  // o/Wo reads done
        stage_w(g_wc_lo, s_w1, tid);
#pragma unroll
        for (int nt = 0; nt < 4; nt++) {
            int cc = nq * 32 + nt * 8 + q2;
            float b0v = __ldg(out_b + cc), b1v = __ldg(out_b + cc + 1);
#pragma unroll
            for (int m = 0; m < 2; m++) {
                int ra = mq * 32 + m * 16 + g, rb = ra + 8;
                float y00 = acc[m][nt][0] + b0v + xf[cc * 132 + ra];
                float y01 = acc[m][nt][1] + b1v + xf[(cc + 1) * 132 + ra];
                float y10 = acc[m][nt][2] + b0v + xf[cc * 132 + rb];
                float y11 = acc[m][nt][3] + b1v + xf[(cc + 1) * 132 + rb];
                float h00 = __bfloat162float(__float2bfloat16(y00));
                float h01 = __bfloat162float(__float2bfloat16(y01));
                float h10 = __bfloat162float(__float2bfloat16(y10));
                float h11 = __bfloat162float(__float2bfloat16(y11));
                *(uint32_t*)(sm + OFF_QS + bl128(ra, cc * 2)) = packbf(y00, y01);
                *(uint32_t*)(sm + OFF_QS + bl128(rb, cc * 2)) = packbf(y10, y11);
                *(uint32_t*)(sm + OFF_KS + bl128(ra, cc * 2)) = packbf(y00 - h00, y01 - h01);
                *(uint32_t*)(sm + OFF_KS + bl128(rb, cc * 2)) = packbf(y10 - h10, y11 - h11);
            }
        }
    }
    CPW0();
    __syncthreads();

    // ======= conv: y_hi@Whi + y_lo@Whi + y_hi@Wlo (weights resident) =======
    {
        float acc[2][4][4] = {};
        gemm128(s_qs, s_w0, oA0, oA1, oW0, oW1, acc);
        gemm128(s_ks, s_w0, oA0, oA1, oW0, oW1, acc);
        gemm128(s_qs, s_w1, oA0, oA1, oW0, oW1, acc);
#pragma unroll
        for (int nt = 0; nt < 4; nt++) {
            int cc = nq * 32 + nt * 8 + q2;
            float b0v = __ldg(conv_b + cc), b1v = __ldg(conv_b + cc + 1);
#pragma unroll
            for (int m = 0; m < 2; m++) {
                int ra = mq * 32 + m * 16 + g, rb = ra + 8;
                xf[cc * 132 + ra]       = acc[m][nt][0] + b0v + xf[cc * 132 + ra];
                xf[(cc + 1) * 132 + ra] = acc[m][nt][1] + b1v + xf[(cc + 1) * 132 + ra];
                xf[cc * 132 + rb]       = acc[m][nt][2] + b0v + xf[cc * 132 + rb];
                xf[(cc + 1) * 132 + rb] = acc[m][nt][3] + b1v + xf[(cc + 1) * 132 + rb];
            }
        }
    }
    __syncthreads();

    // ---- store ----
    float* ob = out + (size_t)b * 128 * 262144;
#pragma unroll
    for (int it = 0; it < 8; it++) {
        int idx = it * 512 + tid;
        int c = idx >> 5, rem = idx & 31;
        int win = rem >> 4, row = rem & 15;
        int dd = row >> 2, hh = row & 3;
        *(float4*)(ob + (size_t)c * 262144 + (size_t)(d0 + dd) * 4096 +
                   (h0 + hh) * 64 + wp + win * 4) =
            *(float4*)(xf + c * 132 + win * 64 + row * 4);
    }
}

extern "C" void kernel_launch(void* const* d_in, const int* in_sizes, int n_in,
                              void* d_out, int out_size) {
    const float* x      = (const float*)d_in[0];
    const float* ln_g   = (const float*)d_in[1];
    const float* ln_b   = (const float*)d_in[2];
    const float* in_w   = (const float*)d_in[3];
    const float* in_b   = (const float*)d_in[4];
    const float* out_w  = (const float*)d_in[5];
    const float* out_b  = (const float*)d_in[6];
    const float* conv_w = (const float*)d_in[7];
    const float* conv_b = (const float*)d_in[8];
    float* out = (float*)d_out;

    convert_weights_kernel<<<192, 256>>>(in_w, out_w, conv_w);

    cudaFuncSetAttribute(fused_wsa3d_kernel,
                         cudaFuncAttributeMaxDynamicSharedMemorySize, SMEM_BYTES);
    cudaFuncSetAttribute(fused_wsa3d_kernel,
                         cudaFuncAttributePreferredSharedMemoryCarveout, 100);
    fused_wsa3d_kernel<<<4096, 512, SMEM_BYTES>>>(x, ln_g, ln_b, in_b, out_b,
                                                  conv_b, out);
}

// round 8
// speedup vs baseline: 1.7498x; 1.1545x over previous
#include <cuda_runtime.h>
#include <cuda_bf16.h>
#include <cstdint>

// ---------------------------------------------------------------------------
// v7 = v3 (best measured: 711us) with weight stages hidden behind epilogues.
// 2 windows per CTA (M=128 GEMMs), 512 threads, 4096 CTAs.
// ---------------------------------------------------------------------------

#define SMEM_BYTES 210432

#define OFF_XF    0        // f32  [128c][132t]  x residual; final out overlay
#define OFF_W     67584    // bf16 [128][136]    weight stage
#define OFF_AB    102400   // bf16 [128][136]    xn -> vT[c][t] -> y_lo
#define OFF_QS    137216   // bf16 [128][136]    q -> o -> y_hi
#define OFF_KS    172032   // bf16 [128][136]    k -> conv_hi weights
#define OFF_BIAS  206848   // f32 [896]

__device__ __align__(16) __nv_bfloat16 g_win[384 * 128];
__device__ __align__(16) __nv_bfloat16 g_wout[128 * 128];
__device__ __align__(16) __nv_bfloat16 g_wc_hi[128 * 128];
__device__ __align__(16) __nv_bfloat16 g_wc_lo[128 * 128];

__global__ void convert_weights_kernel(const float* __restrict__ win,
                                       const float* __restrict__ wout,
                                       const float* __restrict__ wc) {
    int i = blockIdx.x * blockDim.x + threadIdx.x;
    if (i < 384 * 128) g_win[i] = __float2bfloat16(win[i]);
    if (i < 128 * 128) {
        g_wout[i] = __float2bfloat16(wout[i]);
        float f = wc[i];
        __nv_bfloat16 h = __float2bfloat16(f);
        g_wc_hi[i] = h;
        g_wc_lo[i] = __float2bfloat16(f - __bfloat162float(h));
    }
}

__device__ __forceinline__ void mma16816(float acc[4], uint32_t a0, uint32_t a1,
                                         uint32_t a2, uint32_t a3,
                                         uint32_t b0, uint32_t b1) {
    asm volatile(
        "mma.sync.aligned.m16n8k16.row.col.f32.bf16.bf16.f32 "
        "{%0,%1,%2,%3},{%4,%5,%6,%7},{%8,%9},{%0,%1,%2,%3};\n"
        : "+f"(acc[0]), "+f"(acc[1]), "+f"(acc[2]), "+f"(acc[3])
        : "r"(a0), "r"(a1), "r"(a2), "r"(a3), "r"(b0), "r"(b1));
}

__device__ __forceinline__ uint32_t packbf(float lo, float hi) {
    uint32_t r;
    asm("cvt.rn.bf16x2.f32 %0, %1, %2;" : "=r"(r) : "f"(hi), "f"(lo));
    return r;
}

__device__ __forceinline__ void ldsm4(uint32_t& r0, uint32_t& r1, uint32_t& r2,
                                      uint32_t& r3, uint32_t addr) {
    asm volatile("ldmatrix.sync.aligned.m8n8.x4.shared.b16 {%0,%1,%2,%3},[%4];"
                 : "=r"(r0), "=r"(r1), "=r"(r2), "=r"(r3) : "r"(addr));
}

__device__ __forceinline__ uint32_t su32(const void* p) {
    return (uint32_t)__cvta_generic_to_shared(p);
}

#define CPA16(dst, src) \
    asm volatile("cp.async.cg.shared.global [%0],[%1],16;" ::"r"(dst), "l"(src))
#define CPC() asm volatile("cp.async.commit_group;")
#define CPW(n) asm volatile("cp.async.wait_group %0;" ::"n"(n))

// stage 128x128 bf16 row-major block into smem stride 136 (4 cp.async/thread)
__device__ __forceinline__ void stage_w(const __nv_bfloat16* __restrict__ src,
                                        uint32_t dstu, int tid) {
#pragma unroll
    for (int it = 0; it < 4; it++) {
        int idx = it * 512 + tid;
        int row = idx >> 4, cq = idx & 15;
        CPA16(dstu + row * 272 + cq * 16, src + row * 128 + cq * 8);
    }
}

// D[32][32] += A[32 rows @Au][128] @ B[32 rows @Wu][128]^T, row stride 272B
__device__ __forceinline__ void gemm128(uint32_t Au, uint32_t Wu,
                                        float acc[2][4][4]) {
#pragma unroll
    for (int k = 0; k < 8; k++) {
        uint32_t a0, a1, a2, a3, e0, e1, e2, e3;
        uint32_t b0, b1, b2, b3, c0, c1, c2, c3;
        ldsm4(a0, a1, a2, a3, Au + k * 32);
        ldsm4(e0, e1, e2, e3, Au + 4352 + k * 32);
        ldsm4(b0, b1, b2, b3, Wu + k * 32);
        ldsm4(c0, c1, c2, c3, Wu + 4352 + k * 32);
        mma16816(acc[0][0], a0, a1, a2, a3, b0, b2);
        mma16816(acc[0][1], a0, a1, a2, a3, b1, b3);
        mma16816(acc[0][2], a0, a1, a2, a3, c0, c2);
        mma16816(acc[0][3], a0, a1, a2, a3, c1, c3);
        mma16816(acc[1][0], e0, e1, e2, e3, b0, b2);
        mma16816(acc[1][1], e0, e1, e2, e3, b1, b3);
        mma16816(acc[1][2], e0, e1, e2, e3, c0, c2);
        mma16816(acc[1][3], e0, e1, e2, e3, c1, c3);
    }
}

__global__ void __launch_bounds__(512, 1)
fused_wsa3d_kernel(const float* __restrict__ x,
                   const float* __restrict__ ln_g, const float* __restrict__ ln_b,
                   const float* __restrict__ in_b, const float* __restrict__ out_b,
                   const float* __restrict__ conv_b,
                   float* __restrict__ out) {
    extern __shared__ char sm[];
    float* xf = (float*)(sm + OFF_XF);                      // [128c][132t]
    __nv_bfloat16* ab = (__nv_bfloat16*)(sm + OFF_AB);
    __nv_bfloat16* qs = (__nv_bfloat16*)(sm + OFF_QS);
    __nv_bfloat16* ks_ = (__nv_bfloat16*)(sm + OFF_KS);
    float* bias = (float*)(sm + OFF_BIAS);

    const int tid = threadIdx.x;
    const int warp = tid >> 5, lane = tid & 31;
    const int g = lane >> 2, q2 = (lane & 3) * 2;
    const int lane16 = lane & 15, laneh = lane >> 4;
    const int mq = warp & 3, nq = warp >> 2;

    const uint32_t s_xf = su32(xf);
    const uint32_t s_ab = su32(ab);
    const uint32_t s_qs = su32(qs);
    const uint32_t s_ks = su32(ks_);
    const uint32_t s_w = su32(sm + OFF_W);
    const uint32_t off136 = (uint32_t)(lane16 * 272 + laneh * 16);

    // window pair coords
    const int widx = blockIdx.x;
    const int b = widx >> 11;
    const int r = widx & 2047;
    const int d0 = (r >> 7) * 4;
    const int h0 = ((r >> 3) & 15) * 4;
    const int wp = (r & 7) * 8;
    const float* xb = x + (size_t)b * 128 * 262144;

    // ---- x load (2 windows) + qkv0 weights + biases ----
#pragma unroll
    for (int it = 0; it < 8; it++) {
        int idx = it * 512 + tid;
        int c = idx >> 5, rem = idx & 31;
        int win = rem >> 4, row = rem & 15;
        int dd = row >> 2, hh = row & 3;
        CPA16(s_xf + (c * 132 + win * 64 + row * 4) * 4,
              xb + (size_t)c * 262144 + (size_t)(d0 + dd) * 4096 +
                  (h0 + hh) * 64 + wp + win * 4);
    }
    CPC();
    stage_w(g_win, s_w, tid);
    CPC();
    for (int i = tid; i < 896; i += 512) {
        float v;
        if (i < 128)      v = ln_g[i];
        else if (i < 256) v = ln_b[i - 128];
        else if (i < 640) v = in_b[i - 256];
        else if (i < 768) v = out_b[i - 640];
        else              v = conv_b[i - 768];
        bias[i] = v;
    }
    CPW(1);
    __syncthreads();

    // ---- LayerNorm (4 threads / token, 128 tokens) ----
    {
        int t = tid >> 2, j = tid & 3;
        float s = 0.f, s2 = 0.f;
#pragma unroll
        for (int i = 0; i < 32; i++) {
            float v = xf[(j + 4 * i) * 132 + t];
            s += v; s2 += v * v;
        }
        s  += __shfl_xor_sync(0xffffffffu, s, 1);
        s  += __shfl_xor_sync(0xffffffffu, s, 2);
        s2 += __shfl_xor_sync(0xffffffffu, s2, 1);
        s2 += __shfl_xor_sync(0xffffffffu, s2, 2);
        float mu = s * (1.f / 128.f);
        float var = s2 * (1.f / 128.f) - mu * mu;
        float rstd = rsqrtf(var + 1e-5f);
#pragma unroll
        for (int i = 0; i < 32; i++) {
            int c = j + 4 * i;
            float v = (xf[c * 132 + t] - mu) * rstd * bias[c] + bias[128 + c];
            ab[t * 136 + c] = __float2bfloat16(v);
        }
    }
    CPW(0);
    __syncthreads();

    const uint32_t Aab = s_ab + mq * 32 * 272 + off136;
    const uint32_t Aqs = s_qs + mq * 32 * 272 + off136;
    const uint32_t Wn = s_w + nq * 32 * 272 + off136;
    const uint32_t Wk = s_ks + nq * 32 * 272 + off136;

    // ---- Q = xn @ Win0 ; Wk staged under epilogue ----
    {
        float acc[2][4][4] = {};
        gemm128(Aab, Wn, acc);
        __syncthreads();                    // all Wq reads done
        stage_w(g_win + 16384, s_w, tid);   // issue Wk
        CPC();
#pragma unroll
        for (int m = 0; m < 2; m++)
#pragma unroll
            for (int nt = 0; nt < 4; nt++) {
                int cc = nq * 32 + nt * 8 + q2;
                int ra = mq * 32 + m * 16 + g, rb = ra + 8;
                float b0 = bias[256 + cc], b1 = bias[256 + cc + 1];
                *(uint32_t*)(qs + ra * 136 + cc) = packbf(acc[m][nt][0] + b0, acc[m][nt][1] + b1);
                *(uint32_t*)(qs + rb * 136 + cc) = packbf(acc[m][nt][2] + b0, acc[m][nt][3] + b1);
            }
    }
    CPW(0);
    __syncthreads();

    // ---- K = xn @ Win1 ; Wv staged under epilogue ----
    {
        float acc[2][4][4] = {};
        gemm128(Aab, Wn, acc);
        __syncthreads();                    // all Wk reads done
        stage_w(g_win + 32768, s_w, tid);   // issue Wv
        CPC();
#pragma unroll
        for (int m = 0; m < 2; m++)
#pragma unroll
            for (int nt = 0; nt < 4; nt++) {
                int cc = nq * 32 + nt * 8 + q2;
                int ra = mq * 32 + m * 16 + g, rb = ra + 8;
                float b0 = bias[384 + cc], b1 = bias[384 + cc + 1];
                *(uint32_t*)(ks_ + ra * 136 + cc) = packbf(acc[m][nt][0] + b0, acc[m][nt][1] + b1);
                *(uint32_t*)(ks_ + rb * 136 + cc) = packbf(acc[m][nt][2] + b0, acc[m][nt][3] + b1);
            }
    }
    CPW(0);
    __syncthreads();

    // ---- V = xn @ Win2 -> vT into ab ; Wo staged under epilogue ----
    {
        float acc[2][4][4] = {};
        gemm128(Aab, Wn, acc);
        __syncthreads();                    // Wv reads + all xn reads done
        stage_w(g_wout, s_w, tid);          // issue Wo
        CPC();
#pragma unroll
        for (int m = 0; m < 2; m++)
#pragma unroll
            for (int nt = 0; nt < 4; nt++) {
                int cc = nq * 32 + nt * 8 + q2;
                int ra = mq * 32 + m * 16 + g, rb = ra + 8;
                float b0 = bias[512 + cc], b1 = bias[512 + cc + 1];
                ab[cc * 136 + ra]       = __float2bfloat16(acc[m][nt][0] + b0);
                ab[(cc + 1) * 136 + ra] = __float2bfloat16(acc[m][nt][1] + b1);
                ab[cc * 136 + rb]       = __float2bfloat16(acc[m][nt][2] + b0);
                ab[(cc + 1) * 136 + rb] = __float2bfloat16(acc[m][nt][3] + b1);
            }
    }
    __syncthreads();  // vT visible (Wo still in flight, waited later)

    // ---- Attention: 32 tasks (win,head,mtile), 2 per warp ----
#pragma unroll 1
    for (int ti = 0; ti < 2; ti++) {
        const int task = warp + ti * 16;
        const int win = task >> 4;
        const int head = (task >> 2) & 3;
        const int mt = task & 3;
        const uint32_t Aq = s_qs + (win * 64 + mt * 16) * 272 + off136 + head * 64;
        const uint32_t Bk = s_ks + (win * 64) * 272 + off136 + head * 64;

        float P[8][4] = {};
#pragma unroll
        for (int k2 = 0; k2 < 2; k2++) {
            uint32_t a0, a1, a2, a3;
            ldsm4(a0, a1, a2, a3, Aq + k2 * 32);
#pragma unroll
            for (int p = 0; p < 4; p++) {
                uint32_t b0, b1, b2, b3;
                ldsm4(b0, b1, b2, b3, Bk + p * 4352 + k2 * 32);
                mma16816(P[2 * p], a0, a1, a2, a3, b0, b2);
                mma16816(P[2 * p + 1], a0, a1, a2, a3, b1, b3);
            }
        }
        const float scale = 0.17677669529663687f;  // 1/sqrt(32)
        float mA = -1e30f, mB = -1e30f;
#pragma unroll
        for (int nt = 0; nt < 8; nt++) {
            mA = fmaxf(mA, fmaxf(P[nt][0], P[nt][1]));
            mB = fmaxf(mB, fmaxf(P[nt][2], P[nt][3]));
        }
        mA = fmaxf(mA, __shfl_xor_sync(0xffffffffu, mA, 1));
        mA = fmaxf(mA, __shfl_xor_sync(0xffffffffu, mA, 2));
        mB = fmaxf(mB, __shfl_xor_sync(0xffffffffu, mB, 1));
        mB = fmaxf(mB, __shfl_xor_sync(0xffffffffu, mB, 2));
        float sA = 0.f, sB = 0.f;
#pragma unroll
        for (int nt = 0; nt < 8; nt++) {
            float e0 = __expf((P[nt][0] - mA) * scale);
            float e1 = __expf((P[nt][1] - mA) * scale);
            float e2 = __expf((P[nt][2] - mB) * scale);
            float e3 = __expf((P[nt][3] - mB) * scale);
            P[nt][0] = e0; P[nt][1] = e1; P[nt][2] = e2; P[nt][3] = e3;
            sA += e0 + e1; sB += e2 + e3;
        }
        sA += __shfl_xor_sync(0xffffffffu, sA, 1);
        sA += __shfl_xor_sync(0xffffffffu, sA, 2);
        sB += __shfl_xor_sync(0xffffffffu, sB, 1);
        sB += __shfl_xor_sync(0xffffffffu, sB, 2);
        float iA = 1.f / sA, iB = 1.f / sB;

        const uint32_t Bv = s_ab + (head * 32) * 272 + off136 + win * 128;
        float accO[4][4] = {};
#pragma unroll
        for (int ks = 0; ks < 4; ks++) {
            uint32_t a0 = packbf(P[2 * ks][0] * iA, P[2 * ks][1] * iA);
            uint32_t a1 = packbf(P[2 * ks][2] * iB, P[2 * ks][3] * iB);
            uint32_t a2 = packbf(P[2 * ks + 1][0] * iA, P[2 * ks + 1][1] * iA);
            uint32_t a3 = packbf(P[2 * ks + 1][2] * iB, P[2 * ks + 1][3] * iB);
            uint32_t b0, b1, b2, b3;
            ldsm4(b0, b1, b2, b3, Bv + ks * 32);
            mma16816(accO[0], a0, a1, a2, a3, b0, b2);
            mma16816(accO[1], a0, a1, a2, a3, b1, b3);
            ldsm4(b0, b1, b2, b3, Bv + 4352 + ks * 32);
            mma16816(accO[2], a0, a1, a2, a3, b0, b2);
            mma16816(accO[3], a0, a1, a2, a3, b1, b3);
        }
        // o -> qs (own task cells only; race-free)
        int ta = win * 64 + mt * 16 + g, tb = ta + 8;
#pragma unroll
        for (int nt = 0; nt < 4; nt++) {
            int cc = head * 32 + nt * 8 + q2;
            *(uint32_t*)(qs + ta * 136 + cc) = packbf(accO[nt][0], accO[nt][1]);
            *(uint32_t*)(qs + tb * 136 + cc) = packbf(accO[nt][2], accO[nt][3]);
        }
    }
    CPW(0);  // Wo staged
    __syncthreads();

    // ---- out_proj (+residual) ; conv_hi stages into ks meanwhile ----
    stage_w(g_wc_hi, s_ks, tid);
    CPC();
    {
        float acc[2][4][4] = {};
        gemm128(Aqs, Wn, acc);  // A = o, B = wout
        __syncthreads();        // all o + Wo reads done
        stage_w(g_wc_lo, s_w, tid);  // wout dead after the barrier
        CPC();
#pragma unroll
        for (int m = 0; m < 2; m++)
#pragma unroll
            for (int nt = 0; nt < 4; nt++) {
                int cc = nq * 32 + nt * 8 + q2;
                int ra = mq * 32 + m * 16 + g, rb = ra + 8;
                float y00 = acc[m][nt][0] + bias[640 + cc]     + xf[cc * 132 + ra];
                float y01 = acc[m][nt][1] + bias[640 + cc + 1] + xf[(cc + 1) * 132 + ra];
                float y10 = acc[m][nt][2] + bias[640 + cc]     + xf[cc * 132 + rb];
                float y11 = acc[m][nt][3] + bias[640 + cc + 1] + xf[(cc + 1) * 132 + rb];
                float h00 = __bfloat162float(__float2bfloat16(y00));
                float h01 = __bfloat162float(__float2bfloat16(y01));
                float h10 = __bfloat162float(__float2bfloat16(y10));
                float h11 = __bfloat162float(__float2bfloat16(y11));
                *(uint32_t*)(qs + ra * 136 + cc) = packbf(y00, y01);
                *(uint32_t*)(qs + rb * 136 + cc) = packbf(y10, y11);
                *(uint32_t*)(ab + ra * 136 + cc) = packbf(y00 - h00, y01 - h01);
                *(uint32_t*)(ab + rb * 136 + cc) = packbf(y10 - h10, y11 - h11);
            }
    }
    CPW(1);  // conv_hi ready (conv_lo may still be in flight)
    __syncthreads();

    // ---- conv: y_hi@Whi + y_lo@Whi + y_hi@Wlo ----
    {
        float acc[2][4][4] = {};
        gemm128(Aqs, Wk, acc);
        gemm128(Aab, Wk, acc);
        CPW(0);  // conv_lo ready
        __syncthreads();
        gemm128(Aqs, Wn, acc);

        // epilogue in place into xf (each thread owns its cells)
#pragma unroll
        for (int m = 0; m < 2; m++)
#pragma unroll
            for (int nt = 0; nt < 4; nt++) {
                int cc = nq * 32 + nt * 8 + q2;
                int ra = mq * 32 + m * 16 + g, rb = ra + 8;
                xf[cc * 132 + ra]       = acc[m][nt][0] + bias[768 + cc]     + xf[cc * 132 + ra];
                xf[(cc + 1) * 132 + ra] = acc[m][nt][1] + bias[768 + cc + 1] + xf[(cc + 1) * 132 + ra];
                xf[cc * 132 + rb]       = acc[m][nt][2] + bias[768 + cc]     + xf[cc * 132 + rb];
                xf[(cc + 1) * 132 + rb] = acc[m][nt][3] + bias[768 + cc + 1] + xf[(cc + 1) * 132 + rb];
            }
    }
    __syncthreads();

    // ---- store ----
    float* ob = out + (size_t)b * 128 * 262144;
#pragma unroll
    for (int it = 0; it < 8; it++) {
        int idx = it * 512 + tid;
        int c = idx >> 5, rem = idx & 31;
        int win = rem >> 4, row = rem & 15;
        int dd = row >> 2, hh = row & 3;
        *(float4*)(ob + (size_t)c * 262144 + (size_t)(d0 + dd) * 4096 +
                   (h0 + hh) * 64 + wp + win * 4) =
            *(float4*)(xf + c * 132 + win * 64 + row * 4);
    }
}

extern "C" void kernel_launch(void* const* d_in, const int* in_sizes, int n_in,
                              void* d_out, int out_size) {
    const float* x      = (const float*)d_in[0];
    const float* ln_g   = (const float*)d_in[1];
    const float* ln_b   = (const float*)d_in[2];
    const float* in_w   = (const float*)d_in[3];
    const float* in_b   = (const float*)d_in[4];
    const float* out_w  = (const float*)d_in[5];
    const float* out_b  = (const float*)d_in[6];
    const float* conv_w = (const float*)d_in[7];
    const float* conv_b = (const float*)d_in[8];
    float* out = (float*)d_out;

    convert_weights_kernel<<<192, 256>>>(in_w, out_w, conv_w);

    cudaFuncSetAttribute(fused_wsa3d_kernel,
                         cudaFuncAttributeMaxDynamicSharedMemorySize, SMEM_BYTES);
    fused_wsa3d_kernel<<<4096, 512, SMEM_BYTES>>>(x, ln_g, ln_b, in_b, out_b,
                                                  conv_b, out);
}